// round 4
// baseline (speedup 1.0000x reference)
#include <cuda_runtime.h>
#include <cstdint>

#define PI  3.14159265358979323846f
#define PIH 1.57079632679489662f
#define IR2 0.70710678118654752f

// 16 MB scratch between passes (fits in L2)
__device__ float2 g_scr[1 << 21];

__device__ __forceinline__ float sin_ap(float x){ float y; asm("sin.approx.f32 %0, %1;" : "=f"(y) : "f"(x)); return y; }
__device__ __forceinline__ float sqrt_ap(float x){ float y; asm("sqrt.approx.f32 %0, %1;" : "=f"(y) : "f"(x)); return y; }
// conflict-free for all strides used (1,4,32,256): injects bits4-5 into 0-1 and bits5-6 into 2-3
__device__ __forceinline__ int swz(int r){ return r ^ ((r >> 4) & 3) ^ (((r >> 5) & 3) << 2); }

// squared-magnitude butterfly: out± = Se+So ± 2c*sqrt(Se*So)
__device__ __forceinline__ void bfly(float& Se, float& So, float c){
    float r  = sqrt_ap(Se * So);
    float T  = c * r;
    float Sp = Se + So;
    Se = fmaxf(fmaf( 2.f, T, Sp), 0.f);
    So = fmaxf(fmaf(-2.f, T, Sp), 0.f);
}

struct Coef { float c1, cH, msH, q0, q1, q2, q3; };

// build all radix-8 twiddles from quarter angle h4 = h1/4
__device__ __forceinline__ Coef mkcoef(float h4){
    Coef k;
    float s4 = sin_ap(h4), c4 = sin_ap(PIH - h4);
    float sH = 2.f * s4 * c4;              // sin(h1/2)
    float cH = fmaf(-2.f * s4, s4, 1.f);   // cos(h1/2)
    k.c1  = fmaf(2.f * cH, cH, -1.f);      // cos(h1)
    k.cH  = cH;  k.msH = -sH;
    k.q0  = c4;                            // cos(h1/4)
    k.q1  = (c4 - s4) * IR2;               // cos(h1/4+pi/4)
    k.q2  = -s4;                           // cos(h1/4+pi/2)
    k.q3  = -(c4 + s4) * IR2;              // cos(h1/4+3pi/4)
    return k;
}

// Pass A order: stage1 pairs bit0, stage2 bit1, stage3 bit2
__device__ __forceinline__ void r8A_apply(float* v, const Coef& k){
    bfly(v[0],v[1],k.c1);  bfly(v[2],v[3],k.c1);  bfly(v[4],v[5],k.c1);  bfly(v[6],v[7],k.c1);
    bfly(v[0],v[2],k.cH);  bfly(v[1],v[3],k.msH); bfly(v[4],v[6],k.cH);  bfly(v[5],v[7],k.msH);
    bfly(v[0],v[4],k.q0);  bfly(v[1],v[5],k.q1);  bfly(v[2],v[6],k.q2);  bfly(v[3],v[7],k.q3);
}
// Pass B order: stage1 pairs bit2, stage2 bit1, stage3 bit0
__device__ __forceinline__ void r8B_apply(float* v, const Coef& k){
    bfly(v[0],v[4],k.c1);  bfly(v[1],v[5],k.c1);  bfly(v[2],v[6],k.c1);  bfly(v[3],v[7],k.c1);
    bfly(v[0],v[2],k.cH);  bfly(v[1],v[3],k.cH);  bfly(v[4],v[6],k.msH); bfly(v[5],v[7],k.msH);
    bfly(v[0],v[1],k.q0);  bfly(v[2],v[3],k.q2);  bfly(v[4],v[5],k.q1);  bfly(v[6],v[7],k.q3);
}

template<int B>
__device__ __forceinline__ void r8A(float2* tile, int t){
    const int   j0   = t & ((1 << B) - 1);
    const int   base = ((t >> B) << (B + 3)) | j0;
    const float h4   = (float)j0 * (PI / (float)(4 << B));
    Coef k = mkcoef(h4);              // lane-independent in pass A
    int idx[8]; float2 v[8]; float a[8];
    #pragma unroll
    for (int n = 0; n < 8; n++){ idx[n] = swz(base + (n << B)); v[n] = tile[idx[n]]; }
    #pragma unroll
    for (int n = 0; n < 8; n++) a[n] = v[n].x;
    r8A_apply(a, k);
    #pragma unroll
    for (int n = 0; n < 8; n++){ v[n].x = a[n]; a[n] = v[n].y; }
    r8A_apply(a, k);
    #pragma unroll
    for (int n = 0; n < 8; n++){ v[n].y = a[n]; tile[idx[n]] = v[n]; }
}

template<int B>
__device__ __forceinline__ void r8B(float2* tile, int t, int R0){
    const int   mtop = (1 << (8 - B)) - 1;
    const int   base = ((t >> B) << (B + 3)) | (t & ((1 << B) - 1));
    const float sc   = PI / (float)(1 << (21 - B));     // quarter-angle scale
    int   rl  = (int)(__brev((unsigned)base) >> 21);
    int   j1  = ((rl & mtop) << 11) + R0;
    float h4x = (float)j1 * sc;
    int idx[8]; float2 v[8]; float a[8];
    #pragma unroll
    for (int n = 0; n < 8; n++){ idx[n] = swz(base + (n << B)); v[n] = tile[idx[n]]; }
    Coef kx = mkcoef(h4x);
    #pragma unroll
    for (int n = 0; n < 8; n++) a[n] = v[n].x;
    r8B_apply(a, kx);
    #pragma unroll
    for (int n = 0; n < 8; n++){ v[n].x = a[n]; a[n] = v[n].y; }
    Coef ky = mkcoef(h4x + sc);       // lane y: j1 + 1
    r8B_apply(a, ky);
    #pragma unroll
    for (int n = 0; n < 8; n++){ v[n].y = a[n]; tile[idx[n]] = v[n]; }
}

// ================= Pass A: stages 1..11 =================
__global__ void __launch_bounds__(256) fftA(const float2* __restrict__ x2){
    __shared__ float2 tile[2048];     // 16 KB
    const int t = threadIdx.x, lb2 = blockIdx.x;   // l = 2*lb2 + lane

    #pragma unroll
    for (int r = t; r < 2048; r += 256){
        int T = (int)(__brev((unsigned)r) >> 21);
        tile[swz(r)] = x2[(T << 10) + lb2];
    }
    __syncthreads();

    // stages (1,2): closed form (twiddles 1 and 0)
    #pragma unroll
    for (int g = t; g < 512; g += 256){
        int b = g << 2;
        int i0 = swz(b), i1 = swz(b+1), i2 = swz(b+2), i3 = swz(b+3);
        float2 e0 = tile[i0], e1 = tile[i1], e2 = tile[i2], e3 = tile[i3];
        float2 w0, w1, w2;
#define G12(L) { \
        float A  = fabsf(e0.L + e1.L), Bv = fabsf(e2.L + e3.L); \
        float d1 = e0.L - e1.L,        d2 = e2.L - e3.L;        \
        float s  = A + Bv,             q  = A - Bv;             \
        w0.L = s * s; w2.L = q * q; w1.L = fmaf(d1, d1, d2 * d2); }
        G12(x) G12(y)
#undef G12
        tile[i0] = w0; tile[i1] = w1; tile[i2] = w2; tile[i3] = w1;
    }
    __syncthreads();

    r8A<2>(tile, t); __syncthreads();   // stages 3,4,5
    r8A<5>(tile, t); __syncthreads();   // stages 6,7,8
    r8A<8>(tile, t); __syncthreads();   // stages 9,10,11

    // store to scratch in pass-B layout: float addr = ((r>>1)<<12) + 4*lb2 + 2*lane + (r&1)
    float* scr = (float*)g_scr;
    #pragma unroll
    for (int r = t; r < 2048; r += 256){
        float2 v = tile[swz(r)];
        int base = ((r >> 1) << 12) + (lb2 << 2) + (r & 1);
        scr[base]     = v.x;
        scr[base + 2] = v.y;
    }
}

// ================= Pass B: stages 12..22 + sqrt + bit-reversed store =================
__global__ void __launch_bounds__(256) fftB(float2* __restrict__ out2){
    __shared__ float2 tile[2048];
    const int t = threadIdx.x, gB = blockIdx.x;
    const int R0 = gB << 1;           // rB = R0 + lane

    #pragma unroll
    for (int l = t; l < 2048; l += 256)
        tile[swz(l)] = g_scr[(gB << 11) + l];
    __syncthreads();

    r8B<8>(tile, t, R0); __syncthreads();   // stages 12,13,14
    r8B<5>(tile, t, R0); __syncthreads();   // stages 15,16,17
    r8B<2>(tile, t, R0); __syncthreads();   // stages 18,19,20

    // final radix-4 (stages 21,22) + sqrt + scatter
    #pragma unroll
    for (int g = t; g < 512; g += 256){
        int b  = g << 2;
        int i0 = swz(b), i1 = swz(b+1), i2 = swz(b+2), i3 = swz(b+3);
        float2 v0 = tile[i0], v1 = tile[i1], v2 = tile[i2], v3 = tile[i3];
        int   rl = (int)(__brev((unsigned)b) >> 21);
        int   j  = ((rl & 0x1FF) << 11) + R0;
        float hh = (float)j * (PI / (float)(1 << 21));    // h/2
        float ax[4], ay[4];
        ax[0]=v0.x; ax[1]=v1.x; ax[2]=v2.x; ax[3]=v3.x;
        ay[0]=v0.y; ay[1]=v1.y; ay[2]=v2.y; ay[3]=v3.y;
        {
            float sH = sin_ap(hh), cH = sin_ap(PIH - hh);
            float c1 = fmaf(-2.f*sH, sH, 1.f);
            bfly(ax[0],ax[2],c1); bfly(ax[1],ax[3],c1);
            bfly(ax[0],ax[1],cH); bfly(ax[2],ax[3],-sH);
        }
        {
            float h2 = hh + (PI / (float)(1 << 21));
            float sH = sin_ap(h2), cH = sin_ap(PIH - h2);
            float c1 = fmaf(-2.f*sH, sH, 1.f);
            bfly(ay[0],ay[2],c1); bfly(ay[1],ay[3],c1);
            bfly(ay[0],ay[1],cH); bfly(ay[2],ay[3],-sH);
        }
        #pragma unroll
        for (int n = 0; n < 4; n++){
            int T = (int)(__brev((unsigned)(b + n)) >> 21);
            float2 o; o.x = sqrt_ap(ax[n]); o.y = sqrt_ap(ay[n]);
            out2[(T << 10) + gB] = o;
        }
    }
}

extern "C" void kernel_launch(void* const* d_in, const int* in_sizes, int n_in,
                              void* d_out, int out_size) {
    const float2* x2 = (const float2*)d_in[0];
    fftA<<<1024, 256>>>(x2);
    fftB<<<1024, 256>>>((float2*)d_out);
}

// round 5
// speedup vs baseline: 1.9831x; 1.9831x over previous
#include <cuda_runtime.h>
#include <cstdint>

#define PI  3.14159265358979323846f
#define PIH 1.57079632679489662f
#define IR2 0.70710678118654752f

// 16 MB scratch between passes (fits in L2)
__device__ float4 g_scr[1 << 20];

__device__ __forceinline__ float sin_ap(float x){ float y; asm("sin.approx.f32 %0, %1;" : "=f"(y) : "f"(x)); return y; }
__device__ __forceinline__ float sqrt_ap(float x){ float y; asm("sqrt.approx.f32 %0, %1;" : "=f"(y) : "f"(x)); return y; }
// conflict-free for float4 tiles at strides 1,4,32,256 (quarter-warp verified)
__device__ __forceinline__ int swz(int r){ return r ^ ((r >> 4) & 3) ^ (((r >> 5) & 3) << 2); }

// squared-magnitude butterfly: out± = Se+So ± 2c*sqrt(Se*So)
__device__ __forceinline__ void bfly(float& Se, float& So, float c){
    float r  = sqrt_ap(Se * So);
    float T  = c * r;
    float Sp = Se + So;
    Se = fmaxf(fmaf( 2.f, T, Sp), 0.f);
    So = fmaxf(fmaf(-2.f, T, Sp), 0.f);
}

struct Coef { float c1, cH, msH, q0, q1, q2, q3; };

// all radix-8 twiddles from quarter angle h4 = h1/4
__device__ __forceinline__ Coef mkcoef(float h4){
    Coef k;
    float s4 = sin_ap(h4), c4 = sin_ap(PIH - h4);
    float sH = 2.f * s4 * c4;              // sin(h1/2)
    float cH = fmaf(-2.f * s4, s4, 1.f);   // cos(h1/2)
    k.c1  = fmaf(2.f * cH, cH, -1.f);      // cos(h1)
    k.cH  = cH;  k.msH = -sH;
    k.q0  = c4;                            // cos(h1/4)
    k.q1  = (c4 - s4) * IR2;               // cos(h1/4+pi/4)
    k.q2  = -s4;                           // cos(h1/4+pi/2)
    k.q3  = -(c4 + s4) * IR2;              // cos(h1/4+3pi/4)
    return k;
}

// Pass A: stages pair ascending bits (bit B, B+1, B+2)
__device__ __forceinline__ void r8A_apply(float* v, const Coef& k){
    bfly(v[0],v[1],k.c1);  bfly(v[2],v[3],k.c1);  bfly(v[4],v[5],k.c1);  bfly(v[6],v[7],k.c1);
    bfly(v[0],v[2],k.cH);  bfly(v[1],v[3],k.msH); bfly(v[4],v[6],k.cH);  bfly(v[5],v[7],k.msH);
    bfly(v[0],v[4],k.q0);  bfly(v[1],v[5],k.q1);  bfly(v[2],v[6],k.q2);  bfly(v[3],v[7],k.q3);
}
// Pass B: stages pair descending bits (bit B+2, B+1, B)
__device__ __forceinline__ void r8B_apply(float* v, const Coef& k){
    bfly(v[0],v[4],k.c1);  bfly(v[1],v[5],k.c1);  bfly(v[2],v[6],k.c1);  bfly(v[3],v[7],k.c1);
    bfly(v[0],v[2],k.cH);  bfly(v[1],v[3],k.cH);  bfly(v[4],v[6],k.msH); bfly(v[5],v[7],k.msH);
    bfly(v[0],v[1],k.q0);  bfly(v[2],v[3],k.q2);  bfly(v[4],v[5],k.q1);  bfly(v[6],v[7],k.q3);
}

// ---- Pass A radix-8 round: stages B+1,B+2,B+3 ; twiddle shared across lanes ----
template<int B>
__device__ __forceinline__ void r8A(float4* tile, int t){
    const int   j0   = t & ((1 << B) - 1);
    const int   base = ((t >> B) << (B + 3)) | j0;
    const float h4   = (float)j0 * (PI / (float)(4 << B));
    Coef k = mkcoef(h4);
    int idx[8]; float4 v[8]; float a[8];
    #pragma unroll
    for (int n = 0; n < 8; n++){ idx[n] = swz(base + (n << B)); v[n] = tile[idx[n]]; }
    #pragma unroll
    for (int n = 0; n < 8; n++) a[n] = v[n].x;
    r8A_apply(a, k);
    #pragma unroll
    for (int n = 0; n < 8; n++){ v[n].x = a[n]; a[n] = v[n].y; }
    r8A_apply(a, k);
    #pragma unroll
    for (int n = 0; n < 8; n++){ v[n].y = a[n]; a[n] = v[n].z; }
    r8A_apply(a, k);
    #pragma unroll
    for (int n = 0; n < 8; n++){ v[n].z = a[n]; a[n] = v[n].w; }
    r8A_apply(a, k);
    #pragma unroll
    for (int n = 0; n < 8; n++){ v[n].w = a[n]; tile[idx[n]] = v[n]; }
}

// ---- Pass B radix-8 round: stages S0..S0+2 (S0 = 20-B), twiddle per lane ----
template<int B>
__device__ __forceinline__ void r8B(float4* tile, int t, int R0){
    const int   mtop = (1 << (8 - B)) - 1;             // = 2^(S0-12)-1
    const int   base = ((t >> B) << (B + 3)) | (t & ((1 << B) - 1));
    const float sc   = PI / (float)(1 << (21 - B));    // quarter-angle unit
    int   rl = (int)(__brev((unsigned)base) >> 21);
    int   jb = ((rl & mtop) << 11) + R0;
    float h0 = (float)jb * sc;
    int idx[8]; float4 v[8]; float a[8];
    #pragma unroll
    for (int n = 0; n < 8; n++){ idx[n] = swz(base + (n << B)); v[n] = tile[idx[n]]; }
    {   Coef k = mkcoef(h0);
        #pragma unroll
        for (int n = 0; n < 8; n++) a[n] = v[n].x;
        r8B_apply(a, k);
        #pragma unroll
        for (int n = 0; n < 8; n++) v[n].x = a[n];
    }
    {   Coef k = mkcoef(h0 + sc);
        #pragma unroll
        for (int n = 0; n < 8; n++) a[n] = v[n].y;
        r8B_apply(a, k);
        #pragma unroll
        for (int n = 0; n < 8; n++) v[n].y = a[n];
    }
    {   Coef k = mkcoef(h0 + 2.f * sc);
        #pragma unroll
        for (int n = 0; n < 8; n++) a[n] = v[n].z;
        r8B_apply(a, k);
        #pragma unroll
        for (int n = 0; n < 8; n++) v[n].z = a[n];
    }
    {   Coef k = mkcoef(h0 + 3.f * sc);
        #pragma unroll
        for (int n = 0; n < 8; n++) a[n] = v[n].w;
        r8B_apply(a, k);
        #pragma unroll
        for (int n = 0; n < 8; n++){ v[n].w = a[n]; tile[idx[n]] = v[n]; }
    }
}

// ================= Pass A: stages 1..11 =================
__global__ void __launch_bounds__(256) fftA(const float4* __restrict__ x4){
    __shared__ float4 tile[2048];             // 32 KB, lanes = 4 consecutive low indices
    const int t   = threadIdx.x;
    const int lb4 = blockIdx.x;               // l = 4*lb4 + lane

    #pragma unroll
    for (int r = t; r < 2048; r += 256){
        int T = (int)(__brev((unsigned)r) >> 21);     // brev11
        tile[swz(r)] = x4[(T << 9) + lb4];
    }
    __syncthreads();

    // stages (1,2): closed form, no transcendentals
    #pragma unroll
    for (int g = t; g < 512; g += 256){
        int b = g << 2;
        int i0 = swz(b), i1 = swz(b + 1), i2 = swz(b + 2), i3 = swz(b + 3);
        float4 e0 = tile[i0], e1 = tile[i1], e2 = tile[i2], e3 = tile[i3];
        float4 w0, w1, w2;
#define G12(L) { \
        float A  = fabsf(e0.L + e1.L), Bv = fabsf(e2.L + e3.L); \
        float d1 = e0.L - e1.L,        d2 = e2.L - e3.L;        \
        float s  = A + Bv,             q  = A - Bv;             \
        w0.L = s * s; w2.L = q * q; w1.L = fmaf(d1, d1, d2 * d2); }
        G12(x) G12(y) G12(z) G12(w)
#undef G12
        tile[i0] = w0; tile[i1] = w1; tile[i2] = w2; tile[i3] = w1;
    }
    __syncthreads();

    r8A<2>(tile, t); __syncthreads();   // stages 3,4,5
    r8A<5>(tile, t); __syncthreads();   // stages 6,7,8
    r8A<8>(tile, t); __syncthreads();   // stages 9,10,11

    // transpose-store to scratch (pass-B layout)
    const float* ts  = (const float*)tile;
    float*       scr = (float*)g_scr;
    #pragma unroll
    for (int e = t; e < 8192; e += 256){
        int r0 = e & 3, li = (e >> 2) & 3, G = e >> 4;
        int r  = (G << 2) | r0;
        scr[(G << 13) + (((lb4 << 2) + li) << 2) + r0] = ts[swz(r) * 4 + li];
    }
}

// ================= Pass B: stages 12..22 + final sqrt + bit-reversed store =================
__global__ void __launch_bounds__(256) fftB(float4* __restrict__ out4){
    __shared__ float4 tile[2048];             // lanes = rB = 4g + k
    const int t  = threadIdx.x;
    const int g  = blockIdx.x;
    const int R0 = g << 2;

    #pragma unroll
    for (int l = t; l < 2048; l += 256)
        tile[swz(l)] = g_scr[(g << 11) + l];
    __syncthreads();

    r8B<8>(tile, t, R0); __syncthreads();   // stages 12,13,14
    r8B<5>(tile, t, R0); __syncthreads();   // stages 15,16,17
    r8B<2>(tile, t, R0); __syncthreads();   // stages 18,19,20

    // final radix-4 (stages 21,22) + sqrt + bit-reversed scatter
    {
        const float hs = PI / (float)(1 << 21);
        #pragma unroll
        for (int gb = t; gb < 512; gb += 256){
            int base = gb << 2;
            int i00 = swz(base), i01 = swz(base + 1), i10 = swz(base + 2), i11 = swz(base + 3);
            int rl = (int)(__brev((unsigned)base) >> 21);
            int jb = ((rl & 511) << 11) + R0;
            float h0 = (float)jb * hs;
            float4 v00 = tile[i00], v01 = tile[i01], v10 = tile[i10], v11 = tile[i11];
#define RLF(L, K) { float h = fmaf((float)K, hs, h0); \
            float sh = sin_ap(h), ch = sin_ap(PIH - h); \
            float c2 = fmaf(-2.f * sh, sh, 1.f); float msh = -sh; \
            bfly(v00.L, v10.L, c2); bfly(v01.L, v11.L, c2); \
            bfly(v00.L, v01.L, ch); bfly(v10.L, v11.L, msh); }
            RLF(x,0) RLF(y,1) RLF(z,2) RLF(w,3)
#undef RLF
#define SQ4(v) make_float4(sqrt_ap(v.x), sqrt_ap(v.y), sqrt_ap(v.z), sqrt_ap(v.w))
            out4[(((int)(__brev((unsigned)(base + 0)) >> 21)) << 9) + g] = SQ4(v00);
            out4[(((int)(__brev((unsigned)(base + 1)) >> 21)) << 9) + g] = SQ4(v01);
            out4[(((int)(__brev((unsigned)(base + 2)) >> 21)) << 9) + g] = SQ4(v10);
            out4[(((int)(__brev((unsigned)(base + 3)) >> 21)) << 9) + g] = SQ4(v11);
#undef SQ4
        }
    }
}

extern "C" void kernel_launch(void* const* d_in, const int* in_sizes, int n_in,
                              void* d_out, int out_size) {
    const float4* x4 = (const float4*)d_in[0];
    fftA<<<512, 256>>>(x4);
    fftB<<<512, 256>>>((float4*)d_out);
}

// round 7
// speedup vs baseline: 2.2140x; 1.1164x over previous
#include <cuda_runtime.h>
#include <cstdint>

#define PI  3.14159265358979323846f
#define PIH 1.57079632679489662f
#define IR2 0.70710678118654752f

// 16 MB scratch between passes (fits in L2)
__device__ float4 g_scr[1 << 20];

__device__ __forceinline__ float sin_ap(float x){ float y; asm("sin.approx.f32 %0, %1;" : "=f"(y) : "f"(x)); return y; }
__device__ __forceinline__ float sqrt_ap(float x){ float y; asm("sqrt.approx.f32 %0, %1;" : "=f"(y) : "f"(x)); return y; }
// conflict-free for float4 tiles at strides 1,4,32,256
__device__ __forceinline__ int swz(int r){ return r ^ ((r >> 4) & 3) ^ (((r >> 5) & 3) << 2); }

// squared-magnitude butterfly; inputs may be tiny-negative from rounding, clamp at product
__device__ __forceinline__ void bfly(float& Se, float& So, float c){
    float r  = sqrt_ap(fmaxf(Se * So, 0.f));
    float T  = c * r;
    float Sp = Se + So;
    Se = fmaf( 2.f, T, Sp);
    So = fmaf(-2.f, T, Sp);
}

struct Coef { float c1, cH, msH, q0, q1, q2, q3; };

// all radix-8 twiddles from quarter angle h4 = h1/4
__device__ __forceinline__ Coef mkcoef(float h4){
    Coef k;
    float s4 = sin_ap(h4), c4 = sin_ap(PIH - h4);
    float sH = 2.f * s4 * c4;
    float cH = fmaf(-2.f * s4, s4, 1.f);
    k.c1  = fmaf(2.f * cH, cH, -1.f);
    k.cH  = cH;  k.msH = -sH;
    k.q0  = c4;
    k.q1  = (c4 - s4) * IR2;
    k.q2  = -s4;
    k.q3  = -(c4 + s4) * IR2;
    return k;
}

// Pass A: stages pair ascending bits
__device__ __forceinline__ void r8A_apply(float* v, const Coef& k){
    bfly(v[0],v[1],k.c1);  bfly(v[2],v[3],k.c1);  bfly(v[4],v[5],k.c1);  bfly(v[6],v[7],k.c1);
    bfly(v[0],v[2],k.cH);  bfly(v[1],v[3],k.msH); bfly(v[4],v[6],k.cH);  bfly(v[5],v[7],k.msH);
    bfly(v[0],v[4],k.q0);  bfly(v[1],v[5],k.q1);  bfly(v[2],v[6],k.q2);  bfly(v[3],v[7],k.q3);
}
// Pass B: stages pair descending bits
__device__ __forceinline__ void r8B_apply(float* v, const Coef& k){
    bfly(v[0],v[4],k.c1);  bfly(v[1],v[5],k.c1);  bfly(v[2],v[6],k.c1);  bfly(v[3],v[7],k.c1);
    bfly(v[0],v[2],k.cH);  bfly(v[1],v[3],k.cH);  bfly(v[4],v[6],k.msH); bfly(v[5],v[7],k.msH);
    bfly(v[0],v[1],k.q0);  bfly(v[2],v[3],k.q2);  bfly(v[4],v[5],k.q1);  bfly(v[6],v[7],k.q3);
}

template<int B>
__device__ __forceinline__ void r8A(float4* tile, int t){
    const int   j0   = t & ((1 << B) - 1);
    const int   base = ((t >> B) << (B + 3)) | j0;
    const float h4   = (float)j0 * (PI / (float)(4 << B));
    Coef k = mkcoef(h4);
    int idx[8]; float4 v[8]; float a[8];
    #pragma unroll
    for (int n = 0; n < 8; n++){ idx[n] = swz(base + (n << B)); v[n] = tile[idx[n]]; }
    #pragma unroll
    for (int n = 0; n < 8; n++) a[n] = v[n].x;
    r8A_apply(a, k);
    #pragma unroll
    for (int n = 0; n < 8; n++){ v[n].x = a[n]; a[n] = v[n].y; }
    r8A_apply(a, k);
    #pragma unroll
    for (int n = 0; n < 8; n++){ v[n].y = a[n]; a[n] = v[n].z; }
    r8A_apply(a, k);
    #pragma unroll
    for (int n = 0; n < 8; n++){ v[n].z = a[n]; a[n] = v[n].w; }
    r8A_apply(a, k);
    #pragma unroll
    for (int n = 0; n < 8; n++){ v[n].w = a[n]; tile[idx[n]] = v[n]; }
}

// generic pass-B radix-8 on registers v4[8] with per-lane twiddles
__device__ __forceinline__ void r8B_regs(float4* v, float h0, float sc){
    float a[8];
    {   Coef k = mkcoef(h0);
        #pragma unroll
        for (int n = 0; n < 8; n++) a[n] = v[n].x;
        r8B_apply(a, k);
        #pragma unroll
        for (int n = 0; n < 8; n++) v[n].x = a[n];
    }
    {   Coef k = mkcoef(h0 + sc);
        #pragma unroll
        for (int n = 0; n < 8; n++) a[n] = v[n].y;
        r8B_apply(a, k);
        #pragma unroll
        for (int n = 0; n < 8; n++) v[n].y = a[n];
    }
    {   Coef k = mkcoef(h0 + 2.f * sc);
        #pragma unroll
        for (int n = 0; n < 8; n++) a[n] = v[n].z;
        r8B_apply(a, k);
        #pragma unroll
        for (int n = 0; n < 8; n++) v[n].z = a[n];
    }
    {   Coef k = mkcoef(h0 + 3.f * sc);
        #pragma unroll
        for (int n = 0; n < 8; n++) a[n] = v[n].w;
        r8B_apply(a, k);
        #pragma unroll
        for (int n = 0; n < 8; n++) v[n].w = a[n];
    }
}

template<int B>
__device__ __forceinline__ void r8B(float4* tile, int t, int R0){
    const int   mtop = (1 << (8 - B)) - 1;
    const int   base = ((t >> B) << (B + 3)) | (t & ((1 << B) - 1));
    const float sc   = PI / (float)(1 << (21 - B));
    int   rl = (int)(__brev((unsigned)base) >> 21);
    int   jb = ((rl & mtop) << 11) + R0;
    float h0 = (float)jb * sc;
    int idx[8]; float4 v[8];
    #pragma unroll
    for (int n = 0; n < 8; n++){ idx[n] = swz(base + (n << B)); v[n] = tile[idx[n]]; }
    r8B_regs(v, h0, sc);
    #pragma unroll
    for (int n = 0; n < 8; n++) tile[idx[n]] = v[n];
}

// ================= Pass A: stages 1..11 =================
// Warp w owns rows [256w, 256w+256) for all phases below stage 8 -> warp-local syncs.
__global__ void __launch_bounds__(256) fftA(const float4* __restrict__ x4){
    __shared__ float4 tile[2048];
    const int t   = threadIdx.x;
    const int lb4 = blockIdx.x;
    const int w   = t >> 5, ln = t & 31;

    // fused load + closed-form stages (1,2): thread handles groups g = 64w+ln, +32
    #pragma unroll
    for (int m = 0; m < 2; m++){
        int g = (w << 6) | ln | (m << 5);
        int b = g << 2;
        float4 e0 = x4[(((int)(__brev((unsigned)(b + 0)) >> 21)) << 9) + lb4];
        float4 e1 = x4[(((int)(__brev((unsigned)(b + 1)) >> 21)) << 9) + lb4];
        float4 e2 = x4[(((int)(__brev((unsigned)(b + 2)) >> 21)) << 9) + lb4];
        float4 e3 = x4[(((int)(__brev((unsigned)(b + 3)) >> 21)) << 9) + lb4];
        float4 w0, w1, w2;
#define G12(L) { \
        float A  = fabsf(e0.L + e1.L), Bv = fabsf(e2.L + e3.L); \
        float d1 = e0.L - e1.L,        d2 = e2.L - e3.L;        \
        float s  = A + Bv,             q  = A - Bv;             \
        w0.L = s * s; w2.L = q * q; w1.L = fmaf(d1, d1, d2 * d2); }
        G12(x) G12(y) G12(z) G12(w)
#undef G12
        tile[swz(b)] = w0; tile[swz(b + 1)] = w1; tile[swz(b + 2)] = w2; tile[swz(b + 3)] = w1;
    }
    __syncwarp();

    r8A<2>(tile, t); __syncwarp();      // stages 3,4,5  (warp-local rows)
    r8A<5>(tile, t); __syncthreads();   // stages 6,7,8  (next round spans all rows)
    r8A<8>(tile, t); __syncthreads();   // stages 9,10,11 (store reads cross-warp)

    // transpose-store to scratch (pass-B layout)
    const float* ts  = (const float*)tile;
    float*       scr = (float*)g_scr;
    #pragma unroll
    for (int e = t; e < 8192; e += 256){
        int r0 = e & 3, li = (e >> 2) & 3, G = e >> 4;
        int r  = (G << 2) | r0;
        scr[(G << 13) + (((lb4 << 2) + li) << 2) + r0] = ts[swz(r) * 4 + li];
    }
}

// ================= Pass B: stages 12..22 + sqrt + bit-reversed store =================
__global__ void __launch_bounds__(256) fftB(float4* __restrict__ out4){
    __shared__ float4 tile[2048];
    const int t  = threadIdx.x;
    const int g  = blockIdx.x;
    const int R0 = g << 2;
    const int w  = t >> 5, ln = t & 31;

    // round 1 (stages 12,13,14): register-forwarded load (rows t + 256n)
    {
        const float sc = PI / (float)(1 << 13);
        float h0 = (float)R0 * sc;       // mtop=0 -> jb = R0
        float4 v[8];
        const float4* src = g_scr + ((long)g << 11) + t;
        #pragma unroll
        for (int n = 0; n < 8; n++) v[n] = src[n << 8];
        r8B_regs(v, h0, sc);
        #pragma unroll
        for (int n = 0; n < 8; n++) tile[swz(t + (n << 8))] = v[n];
    }
    __syncthreads();

    r8B<5>(tile, t, R0); __syncwarp();   // stages 15,16,17 (warp-local)
    r8B<2>(tile, t, R0); __syncwarp();   // stages 18,19,20 (warp-local)

    // final radix-4 (stages 21,22) + sqrt + bit-reversed scatter (warp-local groups)
    {
        const float hs = PI / (float)(1 << 21);
        #pragma unroll
        for (int m = 0; m < 2; m++){
            int gb   = (w << 6) | ln | (m << 5);
            int base = gb << 2;
            int i00 = swz(base), i01 = swz(base + 1), i10 = swz(base + 2), i11 = swz(base + 3);
            int rl = (int)(__brev((unsigned)base) >> 21);
            int jb = ((rl & 511) << 11) + R0;
            float h0 = (float)jb * hs;
            float4 v00 = tile[i00], v01 = tile[i01], v10 = tile[i10], v11 = tile[i11];
#define RLF(L, K) { float h = fmaf((float)K, hs, h0); \
            float sh = sin_ap(h), ch = sin_ap(PIH - h); \
            float c2 = fmaf(-2.f * sh, sh, 1.f); float msh = -sh; \
            bfly(v00.L, v10.L, c2); bfly(v01.L, v11.L, c2); \
            bfly(v00.L, v01.L, ch); bfly(v10.L, v11.L, msh); }
            RLF(x,0) RLF(y,1) RLF(z,2) RLF(w,3)
#undef RLF
#define SQ4(v) make_float4(sqrt_ap(fmaxf(v.x,0.f)), sqrt_ap(fmaxf(v.y,0.f)), \
                           sqrt_ap(fmaxf(v.z,0.f)), sqrt_ap(fmaxf(v.w,0.f)))
            out4[(((int)(__brev((unsigned)(base + 0)) >> 21)) << 9) + g] = SQ4(v00);
            out4[(((int)(__brev((unsigned)(base + 1)) >> 21)) << 9) + g] = SQ4(v01);
            out4[(((int)(__brev((unsigned)(base + 2)) >> 21)) << 9) + g] = SQ4(v10);
            out4[(((int)(__brev((unsigned)(base + 3)) >> 21)) << 9) + g] = SQ4(v11);
#undef SQ4
        }
    }
}

extern "C" void kernel_launch(void* const* d_in, const int* in_sizes, int n_in,
                              void* d_out, int out_size) {
    const float4* x4 = (const float4*)d_in[0];
    fftA<<<512, 256>>>(x4);
    fftB<<<512, 256>>>((float4*)d_out);
}